// round 16
// baseline (speedup 1.0000x reference)
#include <cuda_runtime.h>
#include <cstdint>

#define NN 100000
#define EE 3200000
#define EPAD 8
#define CC 32
#define LL 4
#define GG 512
#define XDIM 8
#define EDIM 4

#define QSTEP 0.0009765625f   // 2^-10
#define QINV  1024.0f
#define QMAXV (32.0f - 0.0009765625f)
#define QMINV (-32.0f)
#define BN_EPS_F 1e-5f
#define GEN_EPS_F 1e-7f
#define LOG2E_F 1.4426950408889634f

// ---------------- scratch (device globals; no allocation allowed) -------------
__device__ float d_h [NN * CC];            // node features
__device__ float d_hb[NN * CC];            // (h + D_bne + eps) * t[l]*log2e
__device__ float d_h2[NN * CC];            // h + agg
__device__ short d_eq[(size_t)(EE + EPAD) * CC];  // CSR-permuted edge rows (64B each)
__device__ int   d_srcp[EE + EPAD];        // CSR-permuted src byte-offsets (src*128)
__device__ int   d_deg[NN];                // zeroed at load; re-zeroed by edge_enc
__device__ int   d_rowptr[NN + 1];
__device__ int   d_wp[NN];
__device__ float d_pool[GG * CC];
__device__ float d_cntf[GG];

// ---------------- helpers ------------------------------------------------------
__device__ __forceinline__ float qf(float x) {
    float y = rintf(x * QINV) * QSTEP;
    return fminf(fmaxf(y, QMINV), QMAXV);
}
__device__ __forceinline__ float ex2f(float x) {
    float y;
    asm("ex2.approx.f32 %0, %1;" : "=f"(y) : "f"(x));
    return y;
}

// ---------------- fused: node encoder + degree hist + pool zero -----------------
__global__ void k_pre(const float* __restrict__ x,
                      const float* __restrict__ Wn,
                      const float* __restrict__ bn_,
                      const float* __restrict__ g,
                      const float* __restrict__ b,
                      const float* __restrict__ m,
                      const float* __restrict__ v,
                      const float* __restrict__ eg,
                      const float* __restrict__ eb,
                      const float* __restrict__ em,
                      const float* __restrict__ ev,
                      const float* __restrict__ t,
                      const int* __restrict__ ei) {
    __shared__ float Ws[XDIM * CC];
    __shared__ float bs[CC], As[CC], Ds[CC], Es[CC];
    int tid = threadIdx.x;
    int gi = blockIdx.x * blockDim.x + tid;

    if (tid < XDIM * CC) Ws[tid] = qf(Wn[tid]);
    if (tid < CC) {
        bs[tid] = qf(bn_[tid]);
        float rs = rsqrtf(v[tid] + BN_EPS_F);
        float a = g[tid] * rs;
        As[tid] = a;
        Ds[tid] = b[tid] - m[tid] * a;
        float ga = eg[tid] * rsqrtf(ev[tid] + BN_EPS_F);
        Es[tid] = eb[tid] - em[tid] * ga + GEN_EPS_F;   // D_bne + eps
    }

    if (gi < GG * CC) d_pool[gi] = 0.0f;
    if (gi < EE) atomicAdd(&d_deg[ei[EE + gi]], 1);

    __syncthreads();
    if (gi >= NN) return;

    float tl2 = __ldg(t) * LOG2E_F;           // t[0]
    const float4* xp = (const float4*)(x + gi * XDIM);
    float4 a0 = xp[0], a1 = xp[1];
    float xq[XDIM];
    xq[0] = qf(a0.x); xq[1] = qf(a0.y); xq[2] = qf(a0.z); xq[3] = qf(a0.w);
    xq[4] = qf(a1.x); xq[5] = qf(a1.y); xq[6] = qf(a1.z); xq[7] = qf(a1.w);
    #pragma unroll
    for (int c = 0; c < CC; c++) {
        float acc = bs[c];
        #pragma unroll
        for (int k = 0; k < XDIM; k++) acc = fmaf(xq[k], Ws[k * CC + c], acc);
        float hv = fmaf(As[c], qf(acc), Ds[c]);
        d_h [gi * CC + c] = hv;
        d_hb[gi * CC + c] = (hv + Es[c]) * tl2;
    }
}

// ---------------- single-launch scan (redundant per-block prefix) ---------------
#define SCAN_NB 98
__global__ void k_scan() {
    __shared__ int sh[1024];
    __shared__ int red[32];
    int tid = threadIdx.x;
    int lane = tid & 31, wid = tid >> 5;
    int bid = blockIdx.x;

    int lim = bid * 1024;
    int acc = 0;
    for (int i = tid; i < lim; i += 1024) acc += d_deg[i];
    #pragma unroll
    for (int o = 16; o > 0; o >>= 1) acc += __shfl_down_sync(0xFFFFFFFF, acc, o);
    if (lane == 0) red[wid] = acc;
    __syncthreads();
    int off;
    {
        int a2 = red[lane];
        #pragma unroll
        for (int o = 16; o > 0; o >>= 1) a2 += __shfl_down_sync(0xFFFFFFFF, a2, o);
        off = __shfl_sync(0xFFFFFFFF, a2, 0);
    }

    int i = bid * 1024 + tid;
    int v = (i < NN) ? d_deg[i] : 0;
    sh[tid] = v;
    __syncthreads();
    for (int o = 1; o < 1024; o <<= 1) {
        int t = (tid >= o) ? sh[tid - o] : 0;
        __syncthreads();
        sh[tid] += t;
        __syncthreads();
    }
    if (i < NN) {
        int r = sh[tid] - v + off;
        d_rowptr[i] = r;
        d_wp[i] = r;
    }
    if (bid == 0 && tid == 0) d_rowptr[NN] = EE;
}

// ---------------- edge encoder + CSR scatter (+ deg reset) ----------------------
__global__ void k_edge_enc(const float* __restrict__ ea,
                           const float* __restrict__ We,
                           const float* __restrict__ be,
                           const int* __restrict__ ei) {
    __shared__ float Ws[EDIM * CC];
    __shared__ float bs[CC];
    int tid = threadIdx.x;
    if (tid < EDIM * CC) Ws[tid] = qf(We[tid]);
    if (tid < CC) bs[tid] = qf(be[tid]);
    __syncthreads();
    int e = blockIdx.x * blockDim.x + tid;
    if (e < NN) d_deg[e] = 0;                 // reset for next call
    if (e >= EE) return;
    float4 a = ((const float4*)ea)[e];
    float x0 = qf(a.x), x1 = qf(a.y), x2 = qf(a.z), x3 = qf(a.w);
    unsigned int us[16];
    #pragma unroll
    for (int c = 0; c < CC; c += 2) {
        float acc0 = bs[c], acc1 = bs[c + 1];
        acc0 = fmaf(x0, Ws[0 * CC + c], acc0);
        acc0 = fmaf(x1, Ws[1 * CC + c], acc0);
        acc0 = fmaf(x2, Ws[2 * CC + c], acc0);
        acc0 = fmaf(x3, Ws[3 * CC + c], acc0);
        acc1 = fmaf(x0, Ws[0 * CC + c + 1], acc1);
        acc1 = fmaf(x1, Ws[1 * CC + c + 1], acc1);
        acc1 = fmaf(x2, Ws[2 * CC + c + 1], acc1);
        acc1 = fmaf(x3, Ws[3 * CC + c + 1], acc1);
        int k0 = __float2int_rn(acc0 * QINV);
        int k1 = __float2int_rn(acc1 * QINV);
        k0 = max(-32768, min(32767, k0));
        k1 = max(-32768, min(32767, k1));
        us[c >> 1] = (unsigned)(k0 & 0xFFFF) | ((unsigned)k1 << 16);
    }
    int src = ei[e];
    int dst = ei[EE + e];
    int pos = atomicAdd(&d_wp[dst], 1);
    d_srcp[pos] = src << 7;                   // byte offset: src * CC * 4
    uint4* o = (uint4*)(d_eq + (size_t)pos * CC);
    __stcs(o + 0, make_uint4(us[0],  us[1],  us[2],  us[3]));
    __stcs(o + 1, make_uint4(us[4],  us[5],  us[6],  us[7]));
    __stcs(o + 2, make_uint4(us[8],  us[9],  us[10], us[11]));
    __stcs(o + 3, make_uint4(us[12], us[13], us[14], us[15]));
}

// ---------------- GENConv softmax agg: half-warp/node, 2 ch/lane ----------------
// Lanes 0-15: node A, lanes 16-31: node B. Each lane handles channels 2c,2c+1.
__global__ void __launch_bounds__(256) k_agg(const float* __restrict__ t, int l,
                      const float* __restrict__ bg, const float* __restrict__ bv) {
    int lane = threadIdx.x & 31;
    int warp = threadIdx.x >> 5;
    int half = lane >> 4;                 // 0 = node A, 1 = node B
    int cl   = lane & 15;                 // channel pair: channels 2cl, 2cl+1
    int node = blockIdx.x * 16 + warp * 2 + half;   // grid covers NN exactly

    float tl2  = __ldg(t + l) * LOG2E_F;
    int c0 = 2 * cl;
    float A20  = QSTEP * __ldg(bg + c0)     * rsqrtf(__ldg(bv + c0)     + BN_EPS_F) * tl2;
    float A21  = QSTEP * __ldg(bg + c0 + 1) * rsqrtf(__ldg(bv + c0 + 1) + BN_EPS_F) * tl2;
    float eps2 = GEN_EPS_F * tl2;

    int p0  = d_rowptr[node];
    int deg = d_rowptr[node + 1] - p0;
    int degO = __shfl_xor_sync(0xFFFFFFFF, deg, 16);
    int trip = max(deg, degO);

    const int*      sp = d_srcp + p0;
    const unsigned* eq = (const unsigned*)d_eq + (size_t)p0 * 16 + cl;  // 16 words/row
    const char*     hl = (const char*)d_hb + c0 * 4;

    float den0 = 0.0f, den1 = 0.0f, num0 = 0.0f, num1 = 0.0f;
    for (int i = 0; i < trip; ++i) {
        int ii = max(0, min(i, deg - 1));
        int off = __ldcs(sp + ii);
        unsigned w = __ldcs(eq + (size_t)ii * 16);
        float2 hb2 = __ldg((const float2*)(hl + off));
        float f0 = (float)(short)(w & 0xFFFF);
        float f1 = (float)(short)(w >> 16);
        float s0 = fmaxf(fmaf(f0, A20, hb2.x), eps2);
        float s1 = fmaxf(fmaf(f1, A21, hb2.y), eps2);
        float e0 = ex2f(s0);
        float e1 = ex2f(s1);
        bool on = (i < deg);
        e0 = on ? e0 : 0.0f;
        e1 = on ? e1 : 0.0f;
        den0 += e0;
        den1 += e1;
        num0 = fmaf(e0, s0, num0);
        num1 = fmaf(e1, s1, num1);
    }
    float inv = 1.0f / tl2;
    float agg0 = num0 / fmaxf(den0, 1e-16f) * inv;
    float agg1 = num1 / fmaxf(den1, 1e-16f) * inv;
    int idx = node * CC + c0;
    float2 hv = *(const float2*)(d_h + idx);
    float2 ov;
    ov.x = hv.x + agg0;
    ov.y = hv.y + agg1;
    *(float2*)(d_h2 + idx) = ov;
}

// ---------------- per-layer quantized MLP, 2 nodes/thread (smem-BW halved) ------
#define MLP_TPB 128
#define MLP_NPB (2 * MLP_TPB)   // 256 nodes per block
__global__ void __launch_bounds__(MLP_TPB) k_mlp(int l,
        const float* __restrict__ W1, const float* __restrict__ b1,
        const float* __restrict__ g1, const float* __restrict__ bb1,
        const float* __restrict__ m1, const float* __restrict__ v1,
        const float* __restrict__ W2, const float* __restrict__ b2,
        const float* __restrict__ eg, const float* __restrict__ eb,
        const float* __restrict__ em, const float* __restrict__ ev,
        const float* __restrict__ t) {
    __shared__ float w1s[CC * 2 * CC];   // [k][j] (j contiguous)
    __shared__ float w2s[2 * CC * CC];   // [j][c] (c contiguous)
    __shared__ float b1s[2 * CC], a1s[2 * CC], d1s[2 * CC], b2s[CC], Es[CC];
    int tid = threadIdx.x;
    const float* W1l = W1 + l * CC * 2 * CC;
    const float* W2l = W2 + l * 2 * CC * CC;
    for (int i = tid; i < CC * 2 * CC; i += MLP_TPB) {
        w1s[i] = qf(W1l[i]);
        w2s[i] = qf(W2l[i]);
    }
    if (tid < 2 * CC) {
        b1s[tid] = qf(b1[l * 2 * CC + tid]);
        float rsv = rsqrtf(v1[l * 2 * CC + tid] + BN_EPS_F);
        float a = g1[l * 2 * CC + tid] * rsv;
        a1s[tid] = a;
        d1s[tid] = bb1[l * 2 * CC + tid] - m1[l * 2 * CC + tid] * a;
    }
    if (tid < CC) {
        b2s[tid] = qf(b2[l * CC + tid]);
        float ga = eg[tid] * rsqrtf(ev[tid] + BN_EPS_F);
        Es[tid] = eb[tid] - em[tid] * ga + GEN_EPS_F;
    }
    __syncthreads();

    int nodeA = blockIdx.x * MLP_NPB + tid;
    if (nodeA >= NN) return;
    int nodeB = nodeA + MLP_TPB;
    bool hasB = (nodeB < NN);
    int nodeBr = hasB ? nodeB : nodeA;      // clamp reads; writes masked

    float xqA[CC], xqB[CC];
    {
        const float4* hpA = (const float4*)(d_h2 + nodeA * CC);
        const float4* hpB = (const float4*)(d_h2 + nodeBr * CC);
        #pragma unroll
        for (int i = 0; i < 8; i++) {
            float4 ta = hpA[i], tb = hpB[i];
            xqA[4 * i + 0] = qf(ta.x); xqA[4 * i + 1] = qf(ta.y);
            xqA[4 * i + 2] = qf(ta.z); xqA[4 * i + 3] = qf(ta.w);
            xqB[4 * i + 0] = qf(tb.x); xqB[4 * i + 1] = qf(tb.y);
            xqB[4 * i + 2] = qf(tb.z); xqB[4 * i + 3] = qf(tb.w);
        }
    }
    float accA[CC], accB[CC];
    #pragma unroll
    for (int c = 0; c < CC; c++) { accA[c] = b2s[c]; accB[c] = b2s[c]; }

    const float4* w1s4 = (const float4*)w1s;   // [k][jb]: w1s4[k*16 + jb/4]
    const float4* w2s4 = (const float4*)w2s;   // [j][cb]: w2s4[j*8 + cb]

    for (int jb = 0; jb < 2 * CC; jb += 4) {
        float aA0 = b1s[jb + 0], aA1 = b1s[jb + 1], aA2 = b1s[jb + 2], aA3 = b1s[jb + 3];
        float aB0 = aA0, aB1 = aA1, aB2 = aA2, aB3 = aA3;
        #pragma unroll
        for (int k = 0; k < CC; k++) {
            float4 w = w1s4[k * 16 + (jb >> 2)];
            float xa = xqA[k], xb = xqB[k];
            aA0 = fmaf(xa, w.x, aA0); aB0 = fmaf(xb, w.x, aB0);
            aA1 = fmaf(xa, w.y, aA1); aB1 = fmaf(xb, w.y, aB1);
            aA2 = fmaf(xa, w.z, aA2); aB2 = fmaf(xb, w.z, aB2);
            aA3 = fmaf(xa, w.w, aA3); aB3 = fmaf(xb, w.w, aB3);
        }
        float zA0 = qf(fmaxf(fmaf(a1s[jb + 0], qf(aA0), d1s[jb + 0]), 0.0f));
        float zA1 = qf(fmaxf(fmaf(a1s[jb + 1], qf(aA1), d1s[jb + 1]), 0.0f));
        float zA2 = qf(fmaxf(fmaf(a1s[jb + 2], qf(aA2), d1s[jb + 2]), 0.0f));
        float zA3 = qf(fmaxf(fmaf(a1s[jb + 3], qf(aA3), d1s[jb + 3]), 0.0f));
        float zB0 = qf(fmaxf(fmaf(a1s[jb + 0], qf(aB0), d1s[jb + 0]), 0.0f));
        float zB1 = qf(fmaxf(fmaf(a1s[jb + 1], qf(aB1), d1s[jb + 1]), 0.0f));
        float zB2 = qf(fmaxf(fmaf(a1s[jb + 2], qf(aB2), d1s[jb + 2]), 0.0f));
        float zB3 = qf(fmaxf(fmaf(a1s[jb + 3], qf(aB3), d1s[jb + 3]), 0.0f));
        #pragma unroll
        for (int cb = 0; cb < 8; cb++) {
            float4 w0 = w2s4[(jb + 0) * 8 + cb];
            accA[4 * cb + 0] = fmaf(zA0, w0.x, accA[4 * cb + 0]);
            accA[4 * cb + 1] = fmaf(zA0, w0.y, accA[4 * cb + 1]);
            accA[4 * cb + 2] = fmaf(zA0, w0.z, accA[4 * cb + 2]);
            accA[4 * cb + 3] = fmaf(zA0, w0.w, accA[4 * cb + 3]);
            accB[4 * cb + 0] = fmaf(zB0, w0.x, accB[4 * cb + 0]);
            accB[4 * cb + 1] = fmaf(zB0, w0.y, accB[4 * cb + 1]);
            accB[4 * cb + 2] = fmaf(zB0, w0.z, accB[4 * cb + 2]);
            accB[4 * cb + 3] = fmaf(zB0, w0.w, accB[4 * cb + 3]);
        }
        #pragma unroll
        for (int cb = 0; cb < 8; cb++) {
            float4 w1v = w2s4[(jb + 1) * 8 + cb];
            accA[4 * cb + 0] = fmaf(zA1, w1v.x, accA[4 * cb + 0]);
            accA[4 * cb + 1] = fmaf(zA1, w1v.y, accA[4 * cb + 1]);
            accA[4 * cb + 2] = fmaf(zA1, w1v.z, accA[4 * cb + 2]);
            accA[4 * cb + 3] = fmaf(zA1, w1v.w, accA[4 * cb + 3]);
            accB[4 * cb + 0] = fmaf(zB1, w1v.x, accB[4 * cb + 0]);
            accB[4 * cb + 1] = fmaf(zB1, w1v.y, accB[4 * cb + 1]);
            accB[4 * cb + 2] = fmaf(zB1, w1v.z, accB[4 * cb + 2]);
            accB[4 * cb + 3] = fmaf(zB1, w1v.w, accB[4 * cb + 3]);
        }
        #pragma unroll
        for (int cb = 0; cb < 8; cb++) {
            float4 w2v = w2s4[(jb + 2) * 8 + cb];
            accA[4 * cb + 0] = fmaf(zA2, w2v.x, accA[4 * cb + 0]);
            accA[4 * cb + 1] = fmaf(zA2, w2v.y, accA[4 * cb + 1]);
            accA[4 * cb + 2] = fmaf(zA2, w2v.z, accA[4 * cb + 2]);
            accA[4 * cb + 3] = fmaf(zA2, w2v.w, accA[4 * cb + 3]);
            accB[4 * cb + 0] = fmaf(zB2, w2v.x, accB[4 * cb + 0]);
            accB[4 * cb + 1] = fmaf(zB2, w2v.y, accB[4 * cb + 1]);
            accB[4 * cb + 2] = fmaf(zB2, w2v.z, accB[4 * cb + 2]);
            accB[4 * cb + 3] = fmaf(zB2, w2v.w, accB[4 * cb + 3]);
        }
        #pragma unroll
        for (int cb = 0; cb < 8; cb++) {
            float4 w3v = w2s4[(jb + 3) * 8 + cb];
            accA[4 * cb + 0] = fmaf(zA3, w3v.x, accA[4 * cb + 0]);
            accA[4 * cb + 1] = fmaf(zA3, w3v.y, accA[4 * cb + 1]);
            accA[4 * cb + 2] = fmaf(zA3, w3v.z, accA[4 * cb + 2]);
            accA[4 * cb + 3] = fmaf(zA3, w3v.w, accA[4 * cb + 3]);
            accB[4 * cb + 0] = fmaf(zB3, w3v.x, accB[4 * cb + 0]);
            accB[4 * cb + 1] = fmaf(zB3, w3v.y, accB[4 * cb + 1]);
            accB[4 * cb + 2] = fmaf(zB3, w3v.z, accB[4 * cb + 2]);
            accB[4 * cb + 3] = fmaf(zB3, w3v.w, accB[4 * cb + 3]);
        }
    }

    bool emit_hb = (l < LL - 1);
    float tl2n = emit_hb ? __ldg(t + l + 1) * LOG2E_F : 0.0f;
    {   // node A writeback
        const float4* ip = (const float4*)(d_h + nodeA * CC);
        float4* op = (float4*)(d_h + nodeA * CC);
        float4* bp = (float4*)(d_hb + nodeA * CC);
        #pragma unroll
        for (int c = 0; c < CC; c += 4) {
            float4 id4 = ip[c >> 2];
            float4 o;
            o.x = qf(accA[c + 0]) + id4.x;
            o.y = qf(accA[c + 1]) + id4.y;
            o.z = qf(accA[c + 2]) + id4.z;
            o.w = qf(accA[c + 3]) + id4.w;
            op[c >> 2] = o;
            if (emit_hb) {
                float4 hbv;
                hbv.x = (o.x + Es[c + 0]) * tl2n;
                hbv.y = (o.y + Es[c + 1]) * tl2n;
                hbv.z = (o.z + Es[c + 2]) * tl2n;
                hbv.w = (o.w + Es[c + 3]) * tl2n;
                bp[c >> 2] = hbv;
            }
        }
    }
    if (hasB) {   // node B writeback
        const float4* ip = (const float4*)(d_h + nodeB * CC);
        float4* op = (float4*)(d_h + nodeB * CC);
        float4* bp = (float4*)(d_hb + nodeB * CC);
        #pragma unroll
        for (int c = 0; c < CC; c += 4) {
            float4 id4 = ip[c >> 2];
            float4 o;
            o.x = qf(accB[c + 0]) + id4.x;
            o.y = qf(accB[c + 1]) + id4.y;
            o.z = qf(accB[c + 2]) + id4.z;
            o.w = qf(accB[c + 3]) + id4.w;
            op[c >> 2] = o;
            if (emit_hb) {
                float4 hbv;
                hbv.x = (o.x + Es[c + 0]) * tl2n;
                hbv.y = (o.y + Es[c + 1]) * tl2n;
                hbv.z = (o.z + Es[c + 2]) * tl2n;
                hbv.w = (o.w + Es[c + 3]) * tl2n;
                bp[c >> 2] = hbv;
            }
        }
    }
}

// ---------------- global mean pool ----------------------------------------------
__global__ void k_pool(const int* __restrict__ batch) {
    int lane = threadIdx.x & 31;
    int w = (blockIdx.x * blockDim.x + threadIdx.x) >> 5;
    const int CHUNK = 128;
    int i0 = w * CHUNK;
    if (i0 >= NN) return;
    int i1 = min(i0 + CHUNK, NN);
    int cur = batch[i0];
    float acc = 0.0f;
    for (int i = i0; i < i1; i++) {
        int g = batch[i];
        float val = d_h[i * CC + lane];
        if (g != cur) {
            atomicAdd(&d_pool[cur * CC + lane], acc);
            acc = 0.0f;
            cur = g;
        }
        acc += val;
    }
    atomicAdd(&d_pool[cur * CC + lane], acc);
}

__global__ void k_cnt(const int* __restrict__ batch) {
    int g = blockIdx.x * blockDim.x + threadIdx.x;
    if (g >= GG) return;
    int lo0 = 0, hi0 = NN;
    while (lo0 < hi0) { int mid = (lo0 + hi0) >> 1; if (batch[mid] < g) lo0 = mid + 1; else hi0 = mid; }
    int lo1 = lo0, hi1 = NN;
    while (lo1 < hi1) { int mid = (lo1 + hi1) >> 1; if (batch[mid] < g + 1) lo1 = mid + 1; else hi1 = mid; }
    d_cntf[g] = (float)(lo1 - lo0);
}

__global__ void k_final(const float* __restrict__ Wo, const float* __restrict__ bo,
                        float* __restrict__ out) {
    __shared__ float wq[CC];
    int tid = threadIdx.x;
    if (tid < CC) wq[tid] = qf(Wo[tid]);
    __syncthreads();
    int g = blockIdx.x * blockDim.x + tid;
    if (g >= GG) return;
    float cnt = fmaxf(d_cntf[g], 1.0f);
    float acc = qf(bo[0]);
    #pragma unroll
    for (int c = 0; c < CC; c++) {
        float pm = d_pool[g * CC + c] / cnt;
        acc = fmaf(qf(pm), wq[c], acc);
    }
    float o = qf(acc);
    float s = 1.0f / (1.0f + expf(-o));
    out[g] = qf(s);
}

// ---------------- launch ---------------------------------------------------------
extern "C" void kernel_launch(void* const* d_in, const int* in_sizes, int n_in,
                              void* d_out, int out_size) {
    const float* x    = (const float*)d_in[0];
    const float* ea   = (const float*)d_in[1];
    const float* Wn   = (const float*)d_in[2];
    const float* bn_  = (const float*)d_in[3];
    const float* We   = (const float*)d_in[4];
    const float* be   = (const float*)d_in[5];
    const float* bnng = (const float*)d_in[6];
    const float* bnnb = (const float*)d_in[7];
    const float* bnnm = (const float*)d_in[8];
    const float* bnnv = (const float*)d_in[9];
    const float* bneg = (const float*)d_in[10];
    const float* bneb = (const float*)d_in[11];
    const float* bnem = (const float*)d_in[12];
    const float* bnev = (const float*)d_in[13];
    const float* t    = (const float*)d_in[14];
    const float* W1   = (const float*)d_in[15];
    const float* b1   = (const float*)d_in[16];
    const float* g1   = (const float*)d_in[17];
    const float* bb1  = (const float*)d_in[18];
    const float* m1   = (const float*)d_in[19];
    const float* v1   = (const float*)d_in[20];
    const float* W2   = (const float*)d_in[21];
    const float* b2   = (const float*)d_in[22];
    const float* Wo   = (const float*)d_in[23];
    const float* bo   = (const float*)d_in[24];
    const int*   ei   = (const int*)d_in[25];
    const int*   batch= (const int*)d_in[26];
    float* out = (float*)d_out;

    k_pre<<<(EE + 255) / 256, 256>>>(x, Wn, bn_, bnng, bnnb, bnnm, bnnv,
                                     bneg, bneb, bnem, bnev, t, ei);
    k_scan<<<SCAN_NB, 1024>>>();
    k_edge_enc<<<(EE + 255) / 256, 256>>>(ea, We, be, ei);

    for (int l = 0; l < LL; l++) {
        k_agg<<<NN / 16, 256>>>(t, l, bneg, bnev);   // 16 nodes per block, exact
        k_mlp<<<(NN + MLP_NPB - 1) / MLP_NPB, MLP_TPB>>>(l, W1, b1, g1, bb1, m1, v1, W2, b2,
                                                         bneg, bneb, bnem, bnev, t);
    }

    k_pool<<<98, 256>>>(batch);
    k_cnt<<<(GG + 255) / 256, 256>>>(batch);
    k_final<<<(GG + 255) / 256, 256>>>(Wo, bo, out);
}

// round 17
// speedup vs baseline: 1.1469x; 1.1469x over previous
#include <cuda_runtime.h>
#include <cstdint>

#define NN 100000
#define EE 3200000
#define CC 32
#define LL 4
#define GG 512
#define XDIM 8
#define EDIM 4

#define QSTEP 0.0009765625f   // 2^-10
#define QINV  1024.0f
#define QMAXV (32.0f - 0.0009765625f)
#define QMINV (-32.0f)
#define BN_EPS_F 1e-5f
#define GEN_EPS_F 1e-7f
#define LOG2E_F 1.4426950408889634f

// ---------------- scratch (device globals; no allocation allowed) -------------
__device__ float d_h [NN * CC];            // node features
__device__ float d_hb[NN * CC];            // (h + D_bne + eps) * t[l]*log2e
__device__ float d_h2[NN * CC];            // h + agg
__device__ short d_eq[(size_t)EE * CC];    // CSR-permuted edge rows (64B each)
__device__ int   d_srcp[EE];               // CSR-permuted src byte-offsets (src*128)
__device__ uint4 d_epk[EE];                // CSR-scattered packs {src<<7, k01, k23, 0}
__device__ int   d_deg[NN];                // zeroed at load; re-zeroed by epack
__device__ int   d_rowptr[NN + 1];
__device__ int   d_wp[NN];
__device__ float d_pool[GG * CC];
__device__ float d_cntf[GG];

// ---------------- helpers ------------------------------------------------------
__device__ __forceinline__ float qf(float x) {
    float y = rintf(x * QINV) * QSTEP;
    return fminf(fmaxf(y, QMINV), QMAXV);
}
__device__ __forceinline__ float ex2f(float x) {
    float y;
    asm("ex2.approx.f32 %0, %1;" : "=f"(y) : "f"(x));
    return y;
}

// ---------------- fused: node encoder + degree hist + pool zero -----------------
__global__ void k_pre(const float* __restrict__ x,
                      const float* __restrict__ Wn,
                      const float* __restrict__ bn_,
                      const float* __restrict__ g,
                      const float* __restrict__ b,
                      const float* __restrict__ m,
                      const float* __restrict__ v,
                      const float* __restrict__ eg,
                      const float* __restrict__ eb,
                      const float* __restrict__ em,
                      const float* __restrict__ ev,
                      const float* __restrict__ t,
                      const int* __restrict__ ei) {
    __shared__ float Ws[XDIM * CC];
    __shared__ float bs[CC], As[CC], Ds[CC], Es[CC];
    int tid = threadIdx.x;
    int gi = blockIdx.x * blockDim.x + tid;

    if (tid < XDIM * CC) Ws[tid] = qf(Wn[tid]);
    if (tid < CC) {
        bs[tid] = qf(bn_[tid]);
        float rs = rsqrtf(v[tid] + BN_EPS_F);
        float a = g[tid] * rs;
        As[tid] = a;
        Ds[tid] = b[tid] - m[tid] * a;
        float ga = eg[tid] * rsqrtf(ev[tid] + BN_EPS_F);
        Es[tid] = eb[tid] - em[tid] * ga + GEN_EPS_F;   // D_bne + eps
    }

    if (gi < GG * CC) d_pool[gi] = 0.0f;
    if (gi < EE) atomicAdd(&d_deg[ei[EE + gi]], 1);

    __syncthreads();
    if (gi >= NN) return;

    float tl2 = __ldg(t) * LOG2E_F;           // t[0]
    const float4* xp = (const float4*)(x + gi * XDIM);
    float4 a0 = xp[0], a1 = xp[1];
    float xq[XDIM];
    xq[0] = qf(a0.x); xq[1] = qf(a0.y); xq[2] = qf(a0.z); xq[3] = qf(a0.w);
    xq[4] = qf(a1.x); xq[5] = qf(a1.y); xq[6] = qf(a1.z); xq[7] = qf(a1.w);
    #pragma unroll
    for (int c = 0; c < CC; c++) {
        float acc = bs[c];
        #pragma unroll
        for (int k = 0; k < XDIM; k++) acc = fmaf(xq[k], Ws[k * CC + c], acc);
        float hv = fmaf(As[c], qf(acc), Ds[c]);
        d_h [gi * CC + c] = hv;
        d_hb[gi * CC + c] = (hv + Es[c]) * tl2;
    }
}

// ---------------- single-launch scan (redundant per-block prefix) ---------------
#define SCAN_NB 98
__global__ void k_scan() {
    __shared__ int sh[1024];
    __shared__ int red[32];
    int tid = threadIdx.x;
    int lane = tid & 31, wid = tid >> 5;
    int bid = blockIdx.x;

    int lim = bid * 1024;
    int acc = 0;
    for (int i = tid; i < lim; i += 1024) acc += d_deg[i];
    #pragma unroll
    for (int o = 16; o > 0; o >>= 1) acc += __shfl_down_sync(0xFFFFFFFF, acc, o);
    if (lane == 0) red[wid] = acc;
    __syncthreads();
    int off;
    {
        int a2 = red[lane];
        #pragma unroll
        for (int o = 16; o > 0; o >>= 1) a2 += __shfl_down_sync(0xFFFFFFFF, a2, o);
        off = __shfl_sync(0xFFFFFFFF, a2, 0);
    }

    int i = bid * 1024 + tid;
    int v = (i < NN) ? d_deg[i] : 0;
    sh[tid] = v;
    __syncthreads();
    for (int o = 1; o < 1024; o <<= 1) {
        int t = (tid >= o) ? sh[tid - o] : 0;
        __syncthreads();
        sh[tid] += t;
        __syncthreads();
    }
    if (i < NN) {
        int r = sh[tid] - v + off;
        d_rowptr[i] = r;
        d_wp[i] = r;
    }
    if (bid == 0 && tid == 0) d_rowptr[NN] = EE;
}

// ---------------- phase 1: pack + CSR scatter (16B/edge) + deg reset ------------
__global__ void k_epack(const float* __restrict__ ea,
                        const int* __restrict__ ei) {
    int e = blockIdx.x * blockDim.x + threadIdx.x;
    if (e < NN) d_deg[e] = 0;                 // reset for next call
    if (e >= EE) return;
    float4 a = ((const float4*)ea)[e];
    int k0 = max(-32768, min(32767, __float2int_rn(a.x * QINV)));
    int k1 = max(-32768, min(32767, __float2int_rn(a.y * QINV)));
    int k2 = max(-32768, min(32767, __float2int_rn(a.z * QINV)));
    int k3 = max(-32768, min(32767, __float2int_rn(a.w * QINV)));
    unsigned y = (unsigned)(k0 & 0xFFFF) | ((unsigned)k1 << 16);
    unsigned z = (unsigned)(k2 & 0xFFFF) | ((unsigned)k3 << 16);
    int src = ei[e];
    int dst = ei[EE + e];
    int pos = atomicAdd(&d_wp[dst], 1);
    __stcs(&d_epk[pos], make_uint4((unsigned)(src << 7), y, z, 0u));  // src*128 bytes
}

// ---------------- phase 2: per-edge expand (sequential read + write) ------------
__global__ void k_eexpand(const float* __restrict__ We,
                          const float* __restrict__ be) {
    __shared__ float Ws[EDIM * CC];   // qf(W) * QSTEP (tick space, exact)
    __shared__ float bs[CC];
    int tid = threadIdx.x;
    if (tid < EDIM * CC) Ws[tid] = qf(We[tid]) * QSTEP;
    if (tid < CC) bs[tid] = qf(be[tid]);
    __syncthreads();
    int e = blockIdx.x * blockDim.x + tid;
    if (e >= EE) return;
    uint4 u = __ldcs(&d_epk[e]);
    d_srcp[e] = (int)u.x;
    float f0 = (float)(short)(u.y & 0xFFFF);
    float f1 = (float)(short)(u.y >> 16);
    float f2 = (float)(short)(u.z & 0xFFFF);
    float f3 = (float)(short)(u.z >> 16);
    unsigned int us[16];
    #pragma unroll
    for (int c = 0; c < CC; c += 2) {
        float acc0 = bs[c], acc1 = bs[c + 1];
        acc0 = fmaf(f0, Ws[0 * CC + c], acc0);
        acc0 = fmaf(f1, Ws[1 * CC + c], acc0);
        acc0 = fmaf(f2, Ws[2 * CC + c], acc0);
        acc0 = fmaf(f3, Ws[3 * CC + c], acc0);
        acc1 = fmaf(f0, Ws[0 * CC + c + 1], acc1);
        acc1 = fmaf(f1, Ws[1 * CC + c + 1], acc1);
        acc1 = fmaf(f2, Ws[2 * CC + c + 1], acc1);
        acc1 = fmaf(f3, Ws[3 * CC + c + 1], acc1);
        int k0 = __float2int_rn(acc0 * QINV);
        int k1 = __float2int_rn(acc1 * QINV);
        k0 = max(-32768, min(32767, k0));
        k1 = max(-32768, min(32767, k1));
        us[c >> 1] = (unsigned)(k0 & 0xFFFF) | ((unsigned)k1 << 16);
    }
    uint4* o = (uint4*)(d_eq + (size_t)e * CC);
    __stcs(o + 0, make_uint4(us[0],  us[1],  us[2],  us[3]));
    __stcs(o + 1, make_uint4(us[4],  us[5],  us[6],  us[7]));
    __stcs(o + 2, make_uint4(us[8],  us[9],  us[10], us[11]));
    __stcs(o + 3, make_uint4(us[12], us[13], us[14], us[15]));
}

// ---------------- GENConv softmax aggregation (R9 champion: max-free, KB=4) -----
__global__ void __launch_bounds__(256) k_agg(const float* __restrict__ t, int l,
                      const float* __restrict__ bg, const float* __restrict__ bv) {
    int lane = threadIdx.x & 31;
    int warp = threadIdx.x >> 5;
    int node = blockIdx.x * 8 + warp;
    if (node >= NN) return;

    float tl2  = __ldg(t + l) * LOG2E_F;
    float A2   = QSTEP * __ldg(bg + lane) * rsqrtf(__ldg(bv + lane) + BN_EPS_F) * tl2;
    float eps2 = GEN_EPS_F * tl2;

    int p0 = d_rowptr[node], p1 = d_rowptr[node + 1];
    const short* eqp = d_eq + (size_t)p0 * CC + lane;
    const char*  hbl = (const char*)d_hb + lane * 4;
    const int*   sp  = d_srcp + p0;

    float den = 0.0f, num = 0.0f;
    int n = p1 - p0;
    int nfull = n & ~3;

    for (int k = 0; k < nfull; k += 4) {
        int o0 = __ldcs(sp + k + 0);
        int o1 = __ldcs(sp + k + 1);
        int o2 = __ldcs(sp + k + 2);
        int o3 = __ldcs(sp + k + 3);
        short q0 = __ldcs(eqp + 0 * CC);
        short q1 = __ldcs(eqp + 1 * CC);
        short q2 = __ldcs(eqp + 2 * CC);
        short q3 = __ldcs(eqp + 3 * CC);
        eqp += 4 * CC;
        float h0 = __ldg((const float*)(hbl + o0));
        float h1 = __ldg((const float*)(hbl + o1));
        float h2 = __ldg((const float*)(hbl + o2));
        float h3 = __ldg((const float*)(hbl + o3));
        float s0 = fmaxf(fmaf((float)q0, A2, h0), eps2);
        float s1 = fmaxf(fmaf((float)q1, A2, h1), eps2);
        float s2 = fmaxf(fmaf((float)q2, A2, h2), eps2);
        float s3 = fmaxf(fmaf((float)q3, A2, h3), eps2);
        float e0 = ex2f(s0);
        float e1 = ex2f(s1);
        float e2 = ex2f(s2);
        float e3 = ex2f(s3);
        den += (e0 + e1) + (e2 + e3);
        num = fmaf(e0, s0, num);
        num = fmaf(e1, s1, num);
        num = fmaf(e2, s2, num);
        num = fmaf(e3, s3, num);
    }
    for (int k = nfull; k < n; ++k) {
        int   off = __ldcs(sp + k);
        short kv  = __ldcs(eqp);
        eqp += CC;
        float hbv = __ldg((const float*)(hbl + off));
        float sl  = fmaxf(fmaf((float)kv, A2, hbv), eps2);
        float e   = ex2f(sl);
        den += e;
        num = fmaf(e, sl, num);
    }
    float agg = num / (fmaxf(den, 1e-16f) * tl2);
    int idx = node * CC + lane;
    d_h2[idx] = d_h[idx] + agg;
}

// ---------------- per-layer quantized MLP, 2 nodes/thread (smem-BW halved) ------
#define MLP_TPB 128
#define MLP_NPB (2 * MLP_TPB)   // 256 nodes per block
__global__ void __launch_bounds__(MLP_TPB) k_mlp(int l,
        const float* __restrict__ W1, const float* __restrict__ b1,
        const float* __restrict__ g1, const float* __restrict__ bb1,
        const float* __restrict__ m1, const float* __restrict__ v1,
        const float* __restrict__ W2, const float* __restrict__ b2,
        const float* __restrict__ eg, const float* __restrict__ eb,
        const float* __restrict__ em, const float* __restrict__ ev,
        const float* __restrict__ t) {
    __shared__ float w1s[CC * 2 * CC];   // [k][j] (j contiguous)
    __shared__ float w2s[2 * CC * CC];   // [j][c] (c contiguous)
    __shared__ float b1s[2 * CC], a1s[2 * CC], d1s[2 * CC], b2s[CC], Es[CC];
    int tid = threadIdx.x;
    const float* W1l = W1 + l * CC * 2 * CC;
    const float* W2l = W2 + l * 2 * CC * CC;
    for (int i = tid; i < CC * 2 * CC; i += MLP_TPB) {
        w1s[i] = qf(W1l[i]);
        w2s[i] = qf(W2l[i]);
    }
    if (tid < 2 * CC) {
        b1s[tid] = qf(b1[l * 2 * CC + tid]);
        float rsv = rsqrtf(v1[l * 2 * CC + tid] + BN_EPS_F);
        float a = g1[l * 2 * CC + tid] * rsv;
        a1s[tid] = a;
        d1s[tid] = bb1[l * 2 * CC + tid] - m1[l * 2 * CC + tid] * a;
    }
    if (tid < CC) {
        b2s[tid] = qf(b2[l * CC + tid]);
        float ga = eg[tid] * rsqrtf(ev[tid] + BN_EPS_F);
        Es[tid] = eb[tid] - em[tid] * ga + GEN_EPS_F;
    }
    __syncthreads();

    int nodeA = blockIdx.x * MLP_NPB + tid;
    if (nodeA >= NN) return;
    int nodeB = nodeA + MLP_TPB;
    bool hasB = (nodeB < NN);
    int nodeBr = hasB ? nodeB : nodeA;      // clamp reads; writes masked

    float xqA[CC], xqB[CC];
    {
        const float4* hpA = (const float4*)(d_h2 + nodeA * CC);
        const float4* hpB = (const float4*)(d_h2 + nodeBr * CC);
        #pragma unroll
        for (int i = 0; i < 8; i++) {
            float4 ta = hpA[i], tb = hpB[i];
            xqA[4 * i + 0] = qf(ta.x); xqA[4 * i + 1] = qf(ta.y);
            xqA[4 * i + 2] = qf(ta.z); xqA[4 * i + 3] = qf(ta.w);
            xqB[4 * i + 0] = qf(tb.x); xqB[4 * i + 1] = qf(tb.y);
            xqB[4 * i + 2] = qf(tb.z); xqB[4 * i + 3] = qf(tb.w);
        }
    }
    float accA[CC], accB[CC];
    #pragma unroll
    for (int c = 0; c < CC; c++) { accA[c] = b2s[c]; accB[c] = b2s[c]; }

    const float4* w1s4 = (const float4*)w1s;   // [k][jb]: w1s4[k*16 + jb/4]
    const float4* w2s4 = (const float4*)w2s;   // [j][cb]: w2s4[j*8 + cb]

    for (int jb = 0; jb < 2 * CC; jb += 4) {
        float aA0 = b1s[jb + 0], aA1 = b1s[jb + 1], aA2 = b1s[jb + 2], aA3 = b1s[jb + 3];
        float aB0 = aA0, aB1 = aA1, aB2 = aA2, aB3 = aA3;
        #pragma unroll
        for (int k = 0; k < CC; k++) {
            float4 w = w1s4[k * 16 + (jb >> 2)];
            float xa = xqA[k], xb = xqB[k];
            aA0 = fmaf(xa, w.x, aA0); aB0 = fmaf(xb, w.x, aB0);
            aA1 = fmaf(xa, w.y, aA1); aB1 = fmaf(xb, w.y, aB1);
            aA2 = fmaf(xa, w.z, aA2); aB2 = fmaf(xb, w.z, aB2);
            aA3 = fmaf(xa, w.w, aA3); aB3 = fmaf(xb, w.w, aB3);
        }
        float zA0 = qf(fmaxf(fmaf(a1s[jb + 0], qf(aA0), d1s[jb + 0]), 0.0f));
        float zA1 = qf(fmaxf(fmaf(a1s[jb + 1], qf(aA1), d1s[jb + 1]), 0.0f));
        float zA2 = qf(fmaxf(fmaf(a1s[jb + 2], qf(aA2), d1s[jb + 2]), 0.0f));
        float zA3 = qf(fmaxf(fmaf(a1s[jb + 3], qf(aA3), d1s[jb + 3]), 0.0f));
        float zB0 = qf(fmaxf(fmaf(a1s[jb + 0], qf(aB0), d1s[jb + 0]), 0.0f));
        float zB1 = qf(fmaxf(fmaf(a1s[jb + 1], qf(aB1), d1s[jb + 1]), 0.0f));
        float zB2 = qf(fmaxf(fmaf(a1s[jb + 2], qf(aB2), d1s[jb + 2]), 0.0f));
        float zB3 = qf(fmaxf(fmaf(a1s[jb + 3], qf(aB3), d1s[jb + 3]), 0.0f));
        #pragma unroll
        for (int cb = 0; cb < 8; cb++) {
            float4 w0 = w2s4[(jb + 0) * 8 + cb];
            accA[4 * cb + 0] = fmaf(zA0, w0.x, accA[4 * cb + 0]);
            accA[4 * cb + 1] = fmaf(zA0, w0.y, accA[4 * cb + 1]);
            accA[4 * cb + 2] = fmaf(zA0, w0.z, accA[4 * cb + 2]);
            accA[4 * cb + 3] = fmaf(zA0, w0.w, accA[4 * cb + 3]);
            accB[4 * cb + 0] = fmaf(zB0, w0.x, accB[4 * cb + 0]);
            accB[4 * cb + 1] = fmaf(zB0, w0.y, accB[4 * cb + 1]);
            accB[4 * cb + 2] = fmaf(zB0, w0.z, accB[4 * cb + 2]);
            accB[4 * cb + 3] = fmaf(zB0, w0.w, accB[4 * cb + 3]);
        }
        #pragma unroll
        for (int cb = 0; cb < 8; cb++) {
            float4 w1v = w2s4[(jb + 1) * 8 + cb];
            accA[4 * cb + 0] = fmaf(zA1, w1v.x, accA[4 * cb + 0]);
            accA[4 * cb + 1] = fmaf(zA1, w1v.y, accA[4 * cb + 1]);
            accA[4 * cb + 2] = fmaf(zA1, w1v.z, accA[4 * cb + 2]);
            accA[4 * cb + 3] = fmaf(zA1, w1v.w, accA[4 * cb + 3]);
            accB[4 * cb + 0] = fmaf(zB1, w1v.x, accB[4 * cb + 0]);
            accB[4 * cb + 1] = fmaf(zB1, w1v.y, accB[4 * cb + 1]);
            accB[4 * cb + 2] = fmaf(zB1, w1v.z, accB[4 * cb + 2]);
            accB[4 * cb + 3] = fmaf(zB1, w1v.w, accB[4 * cb + 3]);
        }
        #pragma unroll
        for (int cb = 0; cb < 8; cb++) {
            float4 w2v = w2s4[(jb + 2) * 8 + cb];
            accA[4 * cb + 0] = fmaf(zA2, w2v.x, accA[4 * cb + 0]);
            accA[4 * cb + 1] = fmaf(zA2, w2v.y, accA[4 * cb + 1]);
            accA[4 * cb + 2] = fmaf(zA2, w2v.z, accA[4 * cb + 2]);
            accA[4 * cb + 3] = fmaf(zA2, w2v.w, accA[4 * cb + 3]);
            accB[4 * cb + 0] = fmaf(zB2, w2v.x, accB[4 * cb + 0]);
            accB[4 * cb + 1] = fmaf(zB2, w2v.y, accB[4 * cb + 1]);
            accB[4 * cb + 2] = fmaf(zB2, w2v.z, accB[4 * cb + 2]);
            accB[4 * cb + 3] = fmaf(zB2, w2v.w, accB[4 * cb + 3]);
        }
        #pragma unroll
        for (int cb = 0; cb < 8; cb++) {
            float4 w3v = w2s4[(jb + 3) * 8 + cb];
            accA[4 * cb + 0] = fmaf(zA3, w3v.x, accA[4 * cb + 0]);
            accA[4 * cb + 1] = fmaf(zA3, w3v.y, accA[4 * cb + 1]);
            accA[4 * cb + 2] = fmaf(zA3, w3v.z, accA[4 * cb + 2]);
            accA[4 * cb + 3] = fmaf(zA3, w3v.w, accA[4 * cb + 3]);
            accB[4 * cb + 0] = fmaf(zB3, w3v.x, accB[4 * cb + 0]);
            accB[4 * cb + 1] = fmaf(zB3, w3v.y, accB[4 * cb + 1]);
            accB[4 * cb + 2] = fmaf(zB3, w3v.z, accB[4 * cb + 2]);
            accB[4 * cb + 3] = fmaf(zB3, w3v.w, accB[4 * cb + 3]);
        }
    }

    bool emit_hb = (l < LL - 1);
    float tl2n = emit_hb ? __ldg(t + l + 1) * LOG2E_F : 0.0f;
    {   // node A writeback
        const float4* ip = (const float4*)(d_h + nodeA * CC);
        float4* op = (float4*)(d_h + nodeA * CC);
        float4* bp = (float4*)(d_hb + nodeA * CC);
        #pragma unroll
        for (int c = 0; c < CC; c += 4) {
            float4 id4 = ip[c >> 2];
            float4 o;
            o.x = qf(accA[c + 0]) + id4.x;
            o.y = qf(accA[c + 1]) + id4.y;
            o.z = qf(accA[c + 2]) + id4.z;
            o.w = qf(accA[c + 3]) + id4.w;
            op[c >> 2] = o;
            if (emit_hb) {
                float4 hbv;
                hbv.x = (o.x + Es[c + 0]) * tl2n;
                hbv.y = (o.y + Es[c + 1]) * tl2n;
                hbv.z = (o.z + Es[c + 2]) * tl2n;
                hbv.w = (o.w + Es[c + 3]) * tl2n;
                bp[c >> 2] = hbv;
            }
        }
    }
    if (hasB) {   // node B writeback
        const float4* ip = (const float4*)(d_h + nodeB * CC);
        float4* op = (float4*)(d_h + nodeB * CC);
        float4* bp = (float4*)(d_hb + nodeB * CC);
        #pragma unroll
        for (int c = 0; c < CC; c += 4) {
            float4 id4 = ip[c >> 2];
            float4 o;
            o.x = qf(accB[c + 0]) + id4.x;
            o.y = qf(accB[c + 1]) + id4.y;
            o.z = qf(accB[c + 2]) + id4.z;
            o.w = qf(accB[c + 3]) + id4.w;
            op[c >> 2] = o;
            if (emit_hb) {
                float4 hbv;
                hbv.x = (o.x + Es[c + 0]) * tl2n;
                hbv.y = (o.y + Es[c + 1]) * tl2n;
                hbv.z = (o.z + Es[c + 2]) * tl2n;
                hbv.w = (o.w + Es[c + 3]) * tl2n;
                bp[c >> 2] = hbv;
            }
        }
    }
}

// ---------------- global mean pool ----------------------------------------------
__global__ void k_pool(const int* __restrict__ batch) {
    int lane = threadIdx.x & 31;
    int w = (blockIdx.x * blockDim.x + threadIdx.x) >> 5;
    const int CHUNK = 128;
    int i0 = w * CHUNK;
    if (i0 >= NN) return;
    int i1 = min(i0 + CHUNK, NN);
    int cur = batch[i0];
    float acc = 0.0f;
    for (int i = i0; i < i1; i++) {
        int g = batch[i];
        float val = d_h[i * CC + lane];
        if (g != cur) {
            atomicAdd(&d_pool[cur * CC + lane], acc);
            acc = 0.0f;
            cur = g;
        }
        acc += val;
    }
    atomicAdd(&d_pool[cur * CC + lane], acc);
}

__global__ void k_cnt(const int* __restrict__ batch) {
    int g = blockIdx.x * blockDim.x + threadIdx.x;
    if (g >= GG) return;
    int lo0 = 0, hi0 = NN;
    while (lo0 < hi0) { int mid = (lo0 + hi0) >> 1; if (batch[mid] < g) lo0 = mid + 1; else hi0 = mid; }
    int lo1 = lo0, hi1 = NN;
    while (lo1 < hi1) { int mid = (lo1 + hi1) >> 1; if (batch[mid] < g + 1) lo1 = mid + 1; else hi1 = mid; }
    d_cntf[g] = (float)(lo1 - lo0);
}

__global__ void k_final(const float* __restrict__ Wo, const float* __restrict__ bo,
                        float* __restrict__ out) {
    __shared__ float wq[CC];
    int tid = threadIdx.x;
    if (tid < CC) wq[tid] = qf(Wo[tid]);
    __syncthreads();
    int g = blockIdx.x * blockDim.x + tid;
    if (g >= GG) return;
    float cnt = fmaxf(d_cntf[g], 1.0f);
    float acc = qf(bo[0]);
    #pragma unroll
    for (int c = 0; c < CC; c++) {
        float pm = d_pool[g * CC + c] / cnt;
        acc = fmaf(qf(pm), wq[c], acc);
    }
    float o = qf(acc);
    float s = 1.0f / (1.0f + expf(-o));
    out[g] = qf(s);
}

// ---------------- launch ---------------------------------------------------------
extern "C" void kernel_launch(void* const* d_in, const int* in_sizes, int n_in,
                              void* d_out, int out_size) {
    const float* x    = (const float*)d_in[0];
    const float* ea   = (const float*)d_in[1];
    const float* Wn   = (const float*)d_in[2];
    const float* bn_  = (const float*)d_in[3];
    const float* We   = (const float*)d_in[4];
    const float* be   = (const float*)d_in[5];
    const float* bnng = (const float*)d_in[6];
    const float* bnnb = (const float*)d_in[7];
    const float* bnnm = (const float*)d_in[8];
    const float* bnnv = (const float*)d_in[9];
    const float* bneg = (const float*)d_in[10];
    const float* bneb = (const float*)d_in[11];
    const float* bnem = (const float*)d_in[12];
    const float* bnev = (const float*)d_in[13];
    const float* t    = (const float*)d_in[14];
    const float* W1   = (const float*)d_in[15];
    const float* b1   = (const float*)d_in[16];
    const float* g1   = (const float*)d_in[17];
    const float* bb1  = (const float*)d_in[18];
    const float* m1   = (const float*)d_in[19];
    const float* v1   = (const float*)d_in[20];
    const float* W2   = (const float*)d_in[21];
    const float* b2   = (const float*)d_in[22];
    const float* Wo   = (const float*)d_in[23];
    const float* bo   = (const float*)d_in[24];
    const int*   ei   = (const int*)d_in[25];
    const int*   batch= (const int*)d_in[26];
    float* out = (float*)d_out;

    k_pre<<<(EE + 255) / 256, 256>>>(x, Wn, bn_, bnng, bnnb, bnnm, bnnv,
                                     bneg, bneb, bnem, bnev, t, ei);
    k_scan<<<SCAN_NB, 1024>>>();
    k_epack<<<(EE + 255) / 256, 256>>>(ea, ei);
    k_eexpand<<<(EE + 255) / 256, 256>>>(We, be);

    for (int l = 0; l < LL; l++) {
        k_agg<<<(NN + 7) / 8, 256>>>(t, l, bneg, bnev);
        k_mlp<<<(NN + MLP_NPB - 1) / MLP_NPB, MLP_TPB>>>(l, W1, b1, g1, bb1, m1, v1, W2, b2,
                                                         bneg, bneb, bnem, bnev, t);
    }

    k_pool<<<98, 256>>>(batch);
    k_cnt<<<(GG + 255) / 256, 256>>>(batch);
    k_final<<<(GG + 255) / 256, 256>>>(Wo, bo, out);
}